// round 9
// baseline (speedup 1.0000x reference)
#include <cuda_runtime.h>
#include <cuda_bf16.h>

#define NN 100000
#define NE 1600000
#define NT_EDGE 1700000   // edges + self loops
#define NG 256
#define NBLK 391          // ceil(NN/256)

// ---------------- scratch (static device allocations; no runtime alloc) ----
__device__ int   g_cnt[NN];
__device__ int   g_fill[NN];
__device__ int   g_rowptr[NN + 1];
__device__ int   g_bsum[NBLK];
__device__ __align__(16) int2  g_edata[NT_EDGE];        // {src, f2i(norm)} by dst
__device__ __align__(256) __nv_bfloat16 g_xpb[NN * 64];  // x padded, bf16, stride 64 (1 line)
__device__ __align__(256) __nv_bfloat16 g_h1b[NN * 64];  // layer1 out bf16 (54 real)
__device__ __align__(256) __nv_bfloat16 g_h2b[NN * 128]; // layer2 out bf16 (108 real)
__device__ __align__(256) __nv_bfloat16 g_h3b[NN * 224]; // layer3 out bf16 (216 real)
__device__ __align__(16) float g_Wp1[56 * 64];
__device__ __align__(16) float g_Wp2[56 * 128];
__device__ __align__(16) float g_Wp3[112 * 224];
__device__ float g_bp1[64], g_bp2[128], g_bp3[224];
__device__ float g_pool[NG * 216];
__device__ int   g_goff[NG + 1];
__device__ float g_g1[NG * 1024];

// ---------------- fused setup: init + padW x3 + x padding(bf16) ----------
#define PW1 (56 * 64 + 64)
#define PW2 (56 * 128 + 128)
#define PW3 (112 * 224 + 224)
#define S0 NN
#define S1 (S0 + PW1)
#define S2 (S1 + PW2)
#define S3 (S2 + PW3)
#define S4 (S3 + NN * 64)

__device__ __forceinline__ void padw_one(int j, const float* W, const float* b,
                                         float* Wp, float* bp, int K, int C,
                                         int KPAD, int CPAD) {
    int tot = KPAD * CPAD;
    if (j < tot) {
        int cc = j % CPAD, kk = j / CPAD;
        Wp[j] = (cc < C && kk < K) ? W[kk * C + cc] : 0.f;
    } else {
        int cc = j - tot;
        bp[cc] = (cc < C) ? b[cc] : 0.f;
    }
}

__global__ void k_setup(const float* __restrict__ x,
                        const float* __restrict__ W1, const float* __restrict__ b1,
                        const float* __restrict__ W2, const float* __restrict__ b2,
                        const float* __restrict__ W3, const float* __restrict__ b3) {
    int i = blockIdx.x * blockDim.x + threadIdx.x;
    if (i < S0) {
        g_cnt[i] = 1;              // self loop
        g_fill[i] = 0;
    } else if (i < S1) {
        padw_one(i - S0, W1, b1, g_Wp1, g_bp1, 54, 54, 56, 64);
    } else if (i < S2) {
        padw_one(i - S1, W2, b2, g_Wp2, g_bp2, 54, 108, 56, 128);
    } else if (i < S3) {
        padw_one(i - S2, W3, b3, g_Wp3, g_bp3, 108, 216, 112, 224);
    } else if (i < S4) {
        int j = i - S3;
        int r = j >> 6, c = j & 63;
        g_xpb[j] = __float2bfloat16((c < 54) ? x[r * 54 + c] : 0.f);
    }
}

// ---------------- fused: degree count + sorted-batch boundary detect ------
__global__ void k_pre(const int* __restrict__ ei, const int* __restrict__ batch) {
    int i = blockIdx.x * blockDim.x + threadIdx.x;
    if (i < NE) {
        atomicAdd(&g_cnt[ei[NE + i]], 1);
    } else if (i < NE + NN) {
        int j = i - NE;
        int bi = batch[j];
        int bprev = (j > 0) ? batch[j - 1] : -1;
        for (int g = bprev + 1; g <= bi; g++) g_goff[g] = j;
        if (j == NN - 1)
            for (int g = bi + 1; g <= NG; g++) g_goff[g] = NN;
    }
}

// ---------------- parallel scan: block sums -> scan sums -> local scan ----
__global__ void k_s1() {            // grid NBLK, block 256
    int b = blockIdx.x, t = threadIdx.x;
    int i = b * 256 + t;
    int v = (i < NN) ? g_cnt[i] : 0;
#pragma unroll
    for (int off = 16; off > 0; off >>= 1)
        v += __shfl_down_sync(0xffffffffu, v, off);
    __shared__ int sm[8];
    if ((t & 31) == 0) sm[t >> 5] = v;
    __syncthreads();
    if (t == 0) {
        int s = 0;
#pragma unroll
        for (int j = 0; j < 8; j++) s += sm[j];
        g_bsum[b] = s;
    }
}

__global__ void k_s2() {            // 1 block, 512 threads: exclusive scan of g_bsum
    __shared__ int p[512];
    int t = threadIdx.x;
    int v = (t < NBLK) ? g_bsum[t] : 0;
    p[t] = v;
    __syncthreads();
    for (int off = 1; off < 512; off <<= 1) {
        int u = (t >= off) ? p[t - off] : 0;
        __syncthreads();
        p[t] += u;
        __syncthreads();
    }
    if (t < NBLK) g_bsum[t] = p[t] - v;   // exclusive
}

__global__ void k_s3() {            // grid NBLK, block 256: local scan + offset
    __shared__ int p[256];
    int b = blockIdx.x, t = threadIdx.x;
    int i = b * 256 + t;
    int v = (i < NN) ? g_cnt[i] : 0;
    p[t] = v;
    __syncthreads();
    for (int off = 1; off < 256; off <<= 1) {
        int u = (t >= off) ? p[t - off] : 0;
        __syncthreads();
        p[t] += u;
        __syncthreads();
    }
    int excl = p[t] - v + g_bsum[b];
    if (i < NN) g_rowptr[i] = excl;
    if (i == NN - 1) g_rowptr[NN] = excl + v;
}

__global__ void k_fill(const int* __restrict__ ei) {
    int i = blockIdx.x * blockDim.x + threadIdx.x;
    if (i >= NT_EDGE) return;
    int r, c;
    if (i < NE) { r = ei[i]; c = ei[NE + i]; }
    else        { r = c = i - NE; }
    float nrm = rsqrtf((float)g_cnt[r] * (float)g_cnt[c]);
    int pos = g_rowptr[c] + atomicAdd(&g_fill[c], 1);
    g_edata[pos] = make_int2(r, __float_as_int(nrm));
}

// ---------------- helpers ----------------
__device__ __forceinline__ unsigned f2tf(float v) {
    unsigned u;
    asm("cvt.rna.tf32.f32 %0, %1;" : "=r"(u) : "f"(v));
    return u;
}

__device__ __forceinline__ void acc8(float acc[8], float nrm, uint4 t) {
    float2 f0 = __bfloat1622float2(*(__nv_bfloat162*)&t.x);
    float2 f1 = __bfloat1622float2(*(__nv_bfloat162*)&t.y);
    float2 f2 = __bfloat1622float2(*(__nv_bfloat162*)&t.z);
    float2 f3 = __bfloat1622float2(*(__nv_bfloat162*)&t.w);
    acc[0] += nrm * f0.x; acc[1] += nrm * f0.y;
    acc[2] += nrm * f1.x; acc[3] += nrm * f1.y;
    acc[4] += nrm * f2.x; acc[5] += nrm * f2.y;
    acc[6] += nrm * f3.x; acc[7] += nrm * f3.y;
}

__device__ __forceinline__ void mma_tf32(float c[4], const unsigned a[4], const unsigned b[2]) {
    asm volatile(
        "mma.sync.aligned.m16n8k8.row.col.f32.tf32.tf32.f32 "
        "{%0,%1,%2,%3}, {%4,%5,%6,%7}, {%8,%9}, {%0,%1,%2,%3};\n"
        : "+f"(c[0]), "+f"(c[1]), "+f"(c[2]), "+f"(c[3])
        : "r"(a[0]), "r"(a[1]), "r"(a[2]), "r"(a[3]), "r"(b[0]), "r"(b[1]));
}

// ---------------- fused aggregate + tf32 GEMM, bf16 output ----------------
// Phase 1: gather/aggregate 64 node rows (bf16, stride SIN) -> As (tf32).
// Phase 2: stage W -> Ws, MMA mainloop, bias+relu epilogue -> bf16 out.
template <int KPAD, int CPAD, int SIN>
__global__ __launch_bounds__(256)
void k_fused(const __nv_bfloat16* __restrict__ in, const float* __restrict__ W,
             const float* __restrict__ bias, __nv_bfloat16* __restrict__ out) {
    extern __shared__ float sm[];
    constexpr int ASTR = KPAD + 2;
    constexpr int WSTR = CPAD + 8;
    constexpr int KCH = 56;
    constexpr int NTILES = CPAD / 32;
    float* As = sm;                       // [64][ASTR]
    float* Ws = sm + 64 * ASTR;           // [KCH][WSTR]

    int tid = threadIdx.x;
    int w = tid >> 5, lane = tid & 31;
    int row0 = blockIdx.x * 64;

    // ---------- phase 1: aggregation into As ----------
    if (SIN == 64) {
        // 1-line rows: 4 edges/warp, 8 lanes (8 els) each
        int q = lane >> 3, sl = lane & 7;
#pragma unroll 1
        for (int rr = w; rr < 64; rr += 8) {
            int node = row0 + rr;
            float acc[8];
#pragma unroll
            for (int j = 0; j < 8; j++) acc[j] = 0.f;
            if (node < NN) {
                int e0 = g_rowptr[node], e1 = g_rowptr[node + 1];
                for (int e = e0; e < e1; e += 4) {
                    int idx = e + q;
                    bool v = idx < e1;
                    int2 ed = __ldg(&g_edata[v ? idx : e]);
                    float nrm = v ? __int_as_float(ed.y) : 0.f;
                    const uint4* src = (const uint4*)(in + (long)ed.x * 64);
                    acc8(acc, nrm, __ldg(&src[sl]));
                }
            }
#pragma unroll
            for (int j = 0; j < 8; j++) {
                acc[j] += __shfl_xor_sync(0xffffffffu, acc[j], 8);
                acc[j] += __shfl_xor_sync(0xffffffffu, acc[j], 16);
            }
            if (q == 0 && sl < 7) {
                float* o = As + rr * ASTR + sl * 8;
#pragma unroll
                for (int j = 0; j < 8; j++) o[j] = __uint_as_float(f2tf(acc[j]));
            }
        }
    } else {
        // 2-line rows: 2 edges/warp, 16 lanes (8 els) each
        int half = lane >> 4, sl = lane & 15;
#pragma unroll 1
        for (int rr = w; rr < 64; rr += 8) {
            int node = row0 + rr;
            float acc[8];
#pragma unroll
            for (int j = 0; j < 8; j++) acc[j] = 0.f;
            if (node < NN) {
                int e0 = g_rowptr[node], e1 = g_rowptr[node + 1];
                for (int e = e0; e < e1; e += 2) {
                    int idx = e + half;
                    bool v = idx < e1;
                    int2 ed = __ldg(&g_edata[v ? idx : e]);
                    float nrm = v ? __int_as_float(ed.y) : 0.f;
                    const uint4* src = (const uint4*)(in + (long)ed.x * SIN);
                    acc8(acc, nrm, __ldg(&src[sl]));
                }
            }
#pragma unroll
            for (int j = 0; j < 8; j++)
                acc[j] += __shfl_xor_sync(0xffffffffu, acc[j], 16);
            if (half == 0 && sl < 14) {
                float* o = As + rr * ASTR + sl * 8;
#pragma unroll
                for (int j = 0; j < 8; j++) o[j] = __uint_as_float(f2tf(acc[j]));
            }
        }
    }
    __syncthreads();

    // ---------- phase 2: GEMM ----------
    int g = lane >> 2, ctg = lane & 3;
    int wm = w & 1, wn = w >> 1;

    float c[2][NTILES][4];
#pragma unroll
    for (int mt = 0; mt < 2; mt++)
#pragma unroll
        for (int nt = 0; nt < NTILES; nt++)
#pragma unroll
            for (int i = 0; i < 4; i++) c[mt][nt][i] = 0.f;

#pragma unroll 1
    for (int kc = 0; kc < KPAD; kc += KCH) {
        constexpr int kchunk = (KPAD < KCH) ? KPAD : KCH;
        for (int i = tid * 4; i < kchunk * CPAD; i += 256 * 4) {
            int kk = i / CPAD, cc = i % CPAD;
            float4 v = *(const float4*)&W[(long)(kc + kk) * CPAD + cc];
            float4 t;
            t.x = __uint_as_float(f2tf(v.x));
            t.y = __uint_as_float(f2tf(v.y));
            t.z = __uint_as_float(f2tf(v.z));
            t.w = __uint_as_float(f2tf(v.w));
            *(float4*)&Ws[kk * WSTR + cc] = t;
        }
        __syncthreads();

#pragma unroll
        for (int ks = 0; ks < kchunk; ks += 8) {
            unsigned a[2][4];
#pragma unroll
            for (int mt = 0; mt < 2; mt++) {
                int ar = wm * 32 + mt * 16;
                int kb = kc + ks + ctg;
                a[mt][0] = __float_as_uint(As[(ar + g) * ASTR + kb]);
                a[mt][1] = __float_as_uint(As[(ar + g + 8) * ASTR + kb]);
                a[mt][2] = __float_as_uint(As[(ar + g) * ASTR + kb + 4]);
                a[mt][3] = __float_as_uint(As[(ar + g + 8) * ASTR + kb + 4]);
            }
            unsigned b[NTILES][2];
#pragma unroll
            for (int nt = 0; nt < NTILES; nt++) {
                int col = wn * (CPAD / 4) + nt * 8 + g;
                b[nt][0] = __float_as_uint(Ws[(ks + ctg) * WSTR + col]);
                b[nt][1] = __float_as_uint(Ws[(ks + ctg + 4) * WSTR + col]);
            }
#pragma unroll
            for (int mt = 0; mt < 2; mt++)
#pragma unroll
                for (int nt = 0; nt < NTILES; nt++)
                    mma_tf32(c[mt][nt], a[mt], b[nt]);
        }
        __syncthreads();
    }

#pragma unroll
    for (int mt = 0; mt < 2; mt++) {
        int r0 = row0 + wm * 32 + mt * 16 + g;
#pragma unroll
        for (int nt = 0; nt < NTILES; nt++) {
            int col = wn * (CPAD / 4) + nt * 8 + 2 * ctg;
            float b0 = bias[col], b1 = bias[col + 1];
            if (r0 < NN)
                *(__nv_bfloat162*)&out[(long)r0 * CPAD + col] =
                    __float22bfloat162_rn(make_float2(
                        fmaxf(c[mt][nt][0] + b0, 0.f), fmaxf(c[mt][nt][1] + b1, 0.f)));
            if (r0 + 8 < NN)
                *(__nv_bfloat162*)&out[(long)(r0 + 8) * CPAD + col] =
                    __float22bfloat162_rn(make_float2(
                        fmaxf(c[mt][nt][2] + b0, 0.f), fmaxf(c[mt][nt][3] + b1, 0.f)));
        }
    }
}

// ---------------- pooling (bf16 in, fp32 accumulate) ----------------
__global__ void k_pool() {    // grid NG, block 224
    int g = blockIdx.x, f = threadIdx.x;
    if (f >= 216) return;
    int v0 = g_goff[g], v1 = g_goff[g + 1];
    float s = 0.f;
    for (int v = v0; v < v1; v++) s += __bfloat162float(g_h3b[(long)v * 224 + f]);
    float cnt = (float)(v1 - v0);
    g_pool[g * 216 + f] = s / fmaxf(cnt, 1.f);
}

// ---------------- tiled MLP head (fp32) ----------------
// mlp1: [256, 216] @ [216, 1024] + bias, relu. grid 128 = 4 row-tiles x 32 col-tiles.
__global__ __launch_bounds__(256) void k_mlp1(const float* __restrict__ Wf1,
                                              const float* __restrict__ bf1) {
    extern __shared__ float smm[];
    float* Pt = smm;            // [64][216]
    float* Wt = smm + 64 * 216; // [216][32]
    int b = blockIdx.x, t = threadIdx.x;
    int bi = b >> 5, bj = b & 31;
    int g0 = bi * 64, c0 = bj * 32;
    for (int i = t; i < 64 * 216; i += 256) {
        int r = i / 216, k = i - r * 216;
        Pt[i] = g_pool[(g0 + r) * 216 + k];
    }
    for (int i = t; i < 216 * 32; i += 256) {
        int k = i >> 5, c = i & 31;
        Wt[i] = Wf1[k * 1024 + c0 + c];
    }
    __syncthreads();
    int c = t & 31, rb = t >> 5;
    float acc[8];
#pragma unroll
    for (int j = 0; j < 8; j++) acc[j] = 0.f;
    for (int k = 0; k < 216; k++) {
        float wv = Wt[k * 32 + c];
#pragma unroll
        for (int j = 0; j < 8; j++)
            acc[j] += Pt[(rb + 8 * j) * 216 + k] * wv;
    }
    float bias = bf1[c0 + c];
#pragma unroll
    for (int j = 0; j < 8; j++)
        g_g1[(g0 + rb + 8 * j) * 1024 + c0 + c] = fmaxf(acc[j] + bias, 0.f);
}

// mlp2: [256, 1024] @ [1024, 128] + bias. grid 16 = 4 row-tiles x 4 col-tiles.
__global__ __launch_bounds__(256) void k_mlp2(const float* __restrict__ Wf2,
                                              const float* __restrict__ bf2,
                                              float* __restrict__ out) {
    __shared__ float At[64 * 128];   // 32KB
    __shared__ float Wt[128 * 32];   // 16KB
    int b = blockIdx.x, t = threadIdx.x;
    int bi = b >> 2, bj = b & 3;
    int g0 = bi * 64, c0 = bj * 32;
    int c = t & 31, rb = t >> 5;
    float acc[8];
#pragma unroll
    for (int j = 0; j < 8; j++) acc[j] = 0.f;
    for (int k0 = 0; k0 < 1024; k0 += 128) {
        for (int i = t; i < 64 * 128; i += 256) {
            int r = i >> 7, k = i & 127;
            At[i] = g_g1[(g0 + r) * 1024 + k0 + k];
        }
        for (int i = t; i < 128 * 32; i += 256) {
            int k = i >> 5, cc = i & 31;
            Wt[i] = Wf2[(k0 + k) * 128 + c0 + cc];
        }
        __syncthreads();
        for (int k = 0; k < 128; k++) {
            float wv = Wt[k * 32 + c];
#pragma unroll
            for (int j = 0; j < 8; j++)
                acc[j] += At[(rb + 8 * j) * 128 + k] * wv;
        }
        __syncthreads();
    }
    float bias = bf2[c0 + c];
#pragma unroll
    for (int j = 0; j < 8; j++)
        out[(g0 + rb + 8 * j) * 128 + c0 + c] = acc[j] + bias;
}

// ---------------- launch ----------------
static int smem_bytes(int KPAD, int CPAD) {
    return (64 * (KPAD + 2) + 56 * (CPAD + 8)) * 4;
}

extern "C" void kernel_launch(void* const* d_in, const int* in_sizes, int n_in,
                              void* d_out, int out_size) {
    const float* x     = (const float*)d_in[0];
    const int*   ei    = (const int*)d_in[1];
    const int*   batch = (const int*)d_in[2];
    const float* W1 = (const float*)d_in[3];
    const float* b1 = (const float*)d_in[4];
    const float* W2 = (const float*)d_in[5];
    const float* b2 = (const float*)d_in[6];
    const float* W3 = (const float*)d_in[7];
    const float* b3 = (const float*)d_in[8];
    const float* Wf1 = (const float*)d_in[9];
    const float* bf1 = (const float*)d_in[10];
    const float* Wf2 = (const float*)d_in[11];
    const float* bf2 = (const float*)d_in[12];
    float* out = (float*)d_out;

    float *Wp1, *bp1, *Wp2, *bp2, *Wp3, *bp3;
    __nv_bfloat16 *xpb, *h1b, *h2b, *h3b;
    cudaGetSymbolAddress((void**)&xpb, g_xpb);
    cudaGetSymbolAddress((void**)&h1b, g_h1b);
    cudaGetSymbolAddress((void**)&h2b, g_h2b);
    cudaGetSymbolAddress((void**)&h3b, g_h3b);
    cudaGetSymbolAddress((void**)&Wp1, g_Wp1);
    cudaGetSymbolAddress((void**)&bp1, g_bp1);
    cudaGetSymbolAddress((void**)&Wp2, g_Wp2);
    cudaGetSymbolAddress((void**)&bp2, g_bp2);
    cudaGetSymbolAddress((void**)&Wp3, g_Wp3);
    cudaGetSymbolAddress((void**)&bp3, g_bp3);

    cudaFuncSetAttribute((const void*)k_fused<56, 64, 64>,
                         cudaFuncAttributeMaxDynamicSharedMemorySize, smem_bytes(56, 64));
    cudaFuncSetAttribute((const void*)k_fused<56, 128, 64>,
                         cudaFuncAttributeMaxDynamicSharedMemorySize, smem_bytes(56, 128));
    cudaFuncSetAttribute((const void*)k_fused<112, 224, 128>,
                         cudaFuncAttributeMaxDynamicSharedMemorySize, smem_bytes(112, 224));
    int mlp1_smem = (64 * 216 + 216 * 32) * 4;
    cudaFuncSetAttribute(k_mlp1, cudaFuncAttributeMaxDynamicSharedMemorySize, mlp1_smem);

    k_setup<<<(S4 + 255) / 256, 256>>>(x, W1, b1, W2, b2, W3, b3);
    k_pre<<<(NE + NN + 255) / 256, 256>>>(ei, batch);
    k_s1<<<NBLK, 256>>>();
    k_s2<<<1, 512>>>();
    k_s3<<<NBLK, 256>>>();
    k_fill<<<(NT_EDGE + 255) / 256, 256>>>(ei);

    int gblk = (NN + 63) / 64;
    // layer 1: gather xpb (bf16,64) + GEMM 56 -> 64 + relu -> h1b (bf16, 64)
    k_fused<56, 64, 64><<<gblk, 256, smem_bytes(56, 64)>>>(xpb, Wp1, bp1, h1b);
    // layer 2: gather h1b + GEMM 56 -> 128 + relu -> h2b (bf16, 128)
    k_fused<56, 128, 64><<<gblk, 256, smem_bytes(56, 128)>>>(h1b, Wp2, bp2, h2b);
    // layer 3: gather h2b (bf16,128) + GEMM 112 -> 224 + relu -> h3b (bf16, 224)
    k_fused<112, 224, 128><<<gblk, 256, smem_bytes(112, 224)>>>(h2b, Wp3, bp3, h3b);

    k_pool<<<NG, 224>>>();
    k_mlp1<<<128, 256, mlp1_smem>>>(Wf1, bf1);
    k_mlp2<<<16, 256>>>(Wf2, bf2, out);
}

// round 10
// speedup vs baseline: 1.0705x; 1.0705x over previous
#include <cuda_runtime.h>
#include <cuda_bf16.h>

#define NN 100000
#define NE 1600000
#define NT_EDGE 1700000   // edges + self loops
#define NG 256
#define NBLK 391          // ceil(NN/256)

// ---------------- scratch (static device allocations; no runtime alloc) ----
__device__ int   g_cnt[NN];
__device__ int   g_fill[NN];
__device__ int   g_rowptr[NN + 1];
__device__ int   g_bsum[NBLK];
__device__ __align__(16) int2  g_edata[NT_EDGE];        // {src, f2i(norm)} by dst
__device__ __align__(256) __nv_bfloat16 g_xpb[NN * 64];  // x padded, bf16, stride 64 (1 line)
__device__ __align__(256) __nv_bfloat16 g_h1b[NN * 64];  // layer1 out bf16 (54 real)
__device__ __align__(256) __nv_bfloat16 g_h2b[NN * 128]; // layer2 out bf16 (108 real)
__device__ __align__(256) __nv_bfloat16 g_h3b[NN * 224]; // layer3 out bf16 (216 real)
__device__ __align__(16) float g_agg[NN * 112];          // aggregation out fp32
__device__ __align__(16) float g_Wp1[56 * 64];
__device__ __align__(16) float g_Wp2[56 * 128];
__device__ __align__(16) float g_Wp3[112 * 224];
__device__ float g_bp1[64], g_bp2[128], g_bp3[224];
__device__ float g_pool[NG * 216];
__device__ int   g_goff[NG + 1];
__device__ float g_g1[NG * 1024];

// ---------------- fused setup: init + padW x3 + x padding(bf16) ----------
#define PW1 (56 * 64 + 64)
#define PW2 (56 * 128 + 128)
#define PW3 (112 * 224 + 224)
#define S0 NN
#define S1 (S0 + PW1)
#define S2 (S1 + PW2)
#define S3 (S2 + PW3)
#define S4 (S3 + NN * 64)

__device__ __forceinline__ void padw_one(int j, const float* W, const float* b,
                                         float* Wp, float* bp, int K, int C,
                                         int KPAD, int CPAD) {
    int tot = KPAD * CPAD;
    if (j < tot) {
        int cc = j % CPAD, kk = j / CPAD;
        Wp[j] = (cc < C && kk < K) ? W[kk * C + cc] : 0.f;
    } else {
        int cc = j - tot;
        bp[cc] = (cc < C) ? b[cc] : 0.f;
    }
}

__global__ void k_setup(const float* __restrict__ x,
                        const float* __restrict__ W1, const float* __restrict__ b1,
                        const float* __restrict__ W2, const float* __restrict__ b2,
                        const float* __restrict__ W3, const float* __restrict__ b3) {
    int i = blockIdx.x * blockDim.x + threadIdx.x;
    if (i < S0) {
        g_cnt[i] = 1;              // self loop
        g_fill[i] = 0;
    } else if (i < S1) {
        padw_one(i - S0, W1, b1, g_Wp1, g_bp1, 54, 54, 56, 64);
    } else if (i < S2) {
        padw_one(i - S1, W2, b2, g_Wp2, g_bp2, 54, 108, 56, 128);
    } else if (i < S3) {
        padw_one(i - S2, W3, b3, g_Wp3, g_bp3, 108, 216, 112, 224);
    } else if (i < S4) {
        int j = i - S3;
        int r = j >> 6, c = j & 63;
        g_xpb[j] = __float2bfloat16((c < 54) ? x[r * 54 + c] : 0.f);
    }
}

// ---------------- fused: degree count + sorted-batch boundary detect ------
__global__ void k_pre(const int* __restrict__ ei, const int* __restrict__ batch) {
    int i = blockIdx.x * blockDim.x + threadIdx.x;
    if (i < NE) {
        atomicAdd(&g_cnt[ei[NE + i]], 1);
    } else if (i < NE + NN) {
        int j = i - NE;
        int bi = batch[j];
        int bprev = (j > 0) ? batch[j - 1] : -1;
        for (int g = bprev + 1; g <= bi; g++) g_goff[g] = j;
        if (j == NN - 1)
            for (int g = bi + 1; g <= NG; g++) g_goff[g] = NN;
    }
}

// ---------------- parallel scan: block sums -> scan sums -> local scan ----
__global__ void k_s1() {            // grid NBLK, block 256
    int b = blockIdx.x, t = threadIdx.x;
    int i = b * 256 + t;
    int v = (i < NN) ? g_cnt[i] : 0;
#pragma unroll
    for (int off = 16; off > 0; off >>= 1)
        v += __shfl_down_sync(0xffffffffu, v, off);
    __shared__ int sm[8];
    if ((t & 31) == 0) sm[t >> 5] = v;
    __syncthreads();
    if (t == 0) {
        int s = 0;
#pragma unroll
        for (int j = 0; j < 8; j++) s += sm[j];
        g_bsum[b] = s;
    }
}

__global__ void k_s2() {            // 1 block, 512 threads: exclusive scan of g_bsum
    __shared__ int p[512];
    int t = threadIdx.x;
    int v = (t < NBLK) ? g_bsum[t] : 0;
    p[t] = v;
    __syncthreads();
    for (int off = 1; off < 512; off <<= 1) {
        int u = (t >= off) ? p[t - off] : 0;
        __syncthreads();
        p[t] += u;
        __syncthreads();
    }
    if (t < NBLK) g_bsum[t] = p[t] - v;   // exclusive
}

__global__ void k_s3() {            // grid NBLK, block 256: local scan + offset
    __shared__ int p[256];
    int b = blockIdx.x, t = threadIdx.x;
    int i = b * 256 + t;
    int v = (i < NN) ? g_cnt[i] : 0;
    p[t] = v;
    __syncthreads();
    for (int off = 1; off < 256; off <<= 1) {
        int u = (t >= off) ? p[t - off] : 0;
        __syncthreads();
        p[t] += u;
        __syncthreads();
    }
    int excl = p[t] - v + g_bsum[b];
    if (i < NN) g_rowptr[i] = excl;
    if (i == NN - 1) g_rowptr[NN] = excl + v;
}

__global__ void k_fill(const int* __restrict__ ei) {
    int i = blockIdx.x * blockDim.x + threadIdx.x;
    if (i >= NT_EDGE) return;
    int r, c;
    if (i < NE) { r = ei[i]; c = ei[NE + i]; }
    else        { r = c = i - NE; }
    float nrm = rsqrtf((float)g_cnt[r] * (float)g_cnt[c]);
    int pos = g_rowptr[c] + atomicAdd(&g_fill[c], 1);
    g_edata[pos] = make_int2(r, __float_as_int(nrm));
}

// ---------------- aggregation (bf16 gather, fp32 accumulate, 2x ILP) ------
__device__ __forceinline__ void acc8(float acc[8], float nrm, uint4 t) {
    float2 f0 = __bfloat1622float2(*(__nv_bfloat162*)&t.x);
    float2 f1 = __bfloat1622float2(*(__nv_bfloat162*)&t.y);
    float2 f2 = __bfloat1622float2(*(__nv_bfloat162*)&t.z);
    float2 f3 = __bfloat1622float2(*(__nv_bfloat162*)&t.w);
    acc[0] += nrm * f0.x; acc[1] += nrm * f0.y;
    acc[2] += nrm * f1.x; acc[3] += nrm * f1.y;
    acc[4] += nrm * f2.x; acc[5] += nrm * f2.y;
    acc[6] += nrm * f3.x; acc[7] += nrm * f3.y;
}

// 64-bf16 rows (128B = 1 line). 8 edges/warp-iter: slots q (4) x 2-deep unroll.
__global__ void k_agg64b(const __nv_bfloat16* __restrict__ in, float* __restrict__ out) {
    int w = (blockIdx.x * blockDim.x + threadIdx.x) >> 5;
    int lane = threadIdx.x & 31;
    if (w >= NN) return;
    int q = lane >> 3, sl = lane & 7;
    int e0 = g_rowptr[w], e1 = g_rowptr[w + 1];
    float acc[8];
#pragma unroll
    for (int j = 0; j < 8; j++) acc[j] = 0.f;
    for (int e = e0; e < e1; e += 8) {
        int i0 = e + q, i1 = e + 4 + q;
        bool v0 = i0 < e1, v1 = i1 < e1;
        int2 ed0 = __ldg(&g_edata[v0 ? i0 : e]);
        int2 ed1 = __ldg(&g_edata[v1 ? i1 : e]);
        float n0 = v0 ? __int_as_float(ed0.y) : 0.f;
        float n1 = v1 ? __int_as_float(ed1.y) : 0.f;
        const uint4* s0 = (const uint4*)(in + (long)ed0.x * 64);
        const uint4* s1 = (const uint4*)(in + (long)ed1.x * 64);
        uint4 t0 = __ldg(&s0[sl]);
        uint4 t1 = __ldg(&s1[sl]);
        acc8(acc, n0, t0);
        acc8(acc, n1, t1);
    }
#pragma unroll
    for (int j = 0; j < 8; j++) {
        acc[j] += __shfl_xor_sync(0xffffffffu, acc[j], 8);
        acc[j] += __shfl_xor_sync(0xffffffffu, acc[j], 16);
    }
    if (q == 0 && sl < 7) {
        float4* o = (float4*)(out + (long)w * 56 + sl * 8);
        o[0] = make_float4(acc[0], acc[1], acc[2], acc[3]);
        o[1] = make_float4(acc[4], acc[5], acc[6], acc[7]);
    }
}

// 128-bf16 rows (256B = 2 lines). 4 edges/warp-iter: slots half (2) x 2-deep.
__global__ void k_agg128b(const __nv_bfloat16* __restrict__ in, float* __restrict__ out) {
    int w = (blockIdx.x * blockDim.x + threadIdx.x) >> 5;
    int lane = threadIdx.x & 31;
    if (w >= NN) return;
    int half = lane >> 4, sl = lane & 15;
    int e0 = g_rowptr[w], e1 = g_rowptr[w + 1];
    float acc[8];
#pragma unroll
    for (int j = 0; j < 8; j++) acc[j] = 0.f;
    for (int e = e0; e < e1; e += 4) {
        int i0 = e + half, i1 = e + 2 + half;
        bool v0 = i0 < e1, v1 = i1 < e1;
        int2 ed0 = __ldg(&g_edata[v0 ? i0 : e]);
        int2 ed1 = __ldg(&g_edata[v1 ? i1 : e]);
        float n0 = v0 ? __int_as_float(ed0.y) : 0.f;
        float n1 = v1 ? __int_as_float(ed1.y) : 0.f;
        const uint4* s0 = (const uint4*)(in + (long)ed0.x * 128);
        const uint4* s1 = (const uint4*)(in + (long)ed1.x * 128);
        uint4 t0 = __ldg(&s0[sl]);
        uint4 t1 = __ldg(&s1[sl]);
        acc8(acc, n0, t0);
        acc8(acc, n1, t1);
    }
#pragma unroll
    for (int j = 0; j < 8; j++)
        acc[j] += __shfl_xor_sync(0xffffffffu, acc[j], 16);
    if (half == 0 && sl < 14) {
        float4* o = (float4*)(out + (long)w * 112 + sl * 8);
        o[0] = make_float4(acc[0], acc[1], acc[2], acc[3]);
        o[1] = make_float4(acc[4], acc[5], acc[6], acc[7]);
    }
}

// ---------------- tf32 tensor-core GEMM, bf16 output ----------------
__device__ __forceinline__ unsigned f2tf(float v) {
    unsigned u;
    asm("cvt.rna.tf32.f32 %0, %1;" : "=r"(u) : "f"(v));
    return u;
}

__device__ __forceinline__ void mma_tf32(float c[4], const unsigned a[4], const unsigned b[2]) {
    asm volatile(
        "mma.sync.aligned.m16n8k8.row.col.f32.tf32.tf32.f32 "
        "{%0,%1,%2,%3}, {%4,%5,%6,%7}, {%8,%9}, {%0,%1,%2,%3};\n"
        : "+f"(c[0]), "+f"(c[1]), "+f"(c[2]), "+f"(c[3])
        : "r"(a[0]), "r"(a[1]), "r"(a[2]), "r"(a[3]), "r"(b[0]), "r"(b[1]));
}

template <int KPAD, int CPAD>
__global__ __launch_bounds__(256)
void k_gemm_mma(const float* __restrict__ A, const float* __restrict__ W,
                const float* __restrict__ bias, __nv_bfloat16* __restrict__ out) {
    extern __shared__ float sm[];
    constexpr int ASTR = KPAD + 2;
    constexpr int WSTR = CPAD + 8;
    constexpr int KCH = 56;
    constexpr int NTILES = CPAD / 32;
    float* As = sm;                       // [64][ASTR]
    float* Ws = sm + 64 * ASTR;           // [KCH][WSTR]

    int tid = threadIdx.x;
    int w = tid >> 5, lane = tid & 31;
    int g = lane >> 2, ctg = lane & 3;
    int wm = w & 1, wn = w >> 1;
    int row0 = blockIdx.x * 64;

    float c[2][NTILES][4];
#pragma unroll
    for (int mt = 0; mt < 2; mt++)
#pragma unroll
        for (int nt = 0; nt < NTILES; nt++)
#pragma unroll
            for (int i = 0; i < 4; i++) c[mt][nt][i] = 0.f;

    for (int i = tid * 4; i < 64 * KPAD; i += 256 * 4) {
        int r = i / KPAD, k = i % KPAD;
        float4 v = make_float4(0.f, 0.f, 0.f, 0.f);
        if (row0 + r < NN) v = *(const float4*)&A[(long)(row0 + r) * KPAD + k];
        As[r * ASTR + k + 0] = __uint_as_float(f2tf(v.x));
        As[r * ASTR + k + 1] = __uint_as_float(f2tf(v.y));
        As[r * ASTR + k + 2] = __uint_as_float(f2tf(v.z));
        As[r * ASTR + k + 3] = __uint_as_float(f2tf(v.w));
    }

#pragma unroll 1
    for (int kc = 0; kc < KPAD; kc += KCH) {
        constexpr int kchunk = (KPAD < KCH) ? KPAD : KCH;
        for (int i = tid * 4; i < kchunk * CPAD; i += 256 * 4) {
            int kk = i / CPAD, cc = i % CPAD;
            float4 v = *(const float4*)&W[(long)(kc + kk) * CPAD + cc];
            float4 t;
            t.x = __uint_as_float(f2tf(v.x));
            t.y = __uint_as_float(f2tf(v.y));
            t.z = __uint_as_float(f2tf(v.z));
            t.w = __uint_as_float(f2tf(v.w));
            *(float4*)&Ws[kk * WSTR + cc] = t;
        }
        __syncthreads();

#pragma unroll
        for (int ks = 0; ks < kchunk; ks += 8) {
            unsigned a[2][4];
#pragma unroll
            for (int mt = 0; mt < 2; mt++) {
                int ar = wm * 32 + mt * 16;
                int kb = kc + ks + ctg;
                a[mt][0] = __float_as_uint(As[(ar + g) * ASTR + kb]);
                a[mt][1] = __float_as_uint(As[(ar + g + 8) * ASTR + kb]);
                a[mt][2] = __float_as_uint(As[(ar + g) * ASTR + kb + 4]);
                a[mt][3] = __float_as_uint(As[(ar + g + 8) * ASTR + kb + 4]);
            }
            unsigned b[NTILES][2];
#pragma unroll
            for (int nt = 0; nt < NTILES; nt++) {
                int col = wn * (CPAD / 4) + nt * 8 + g;
                b[nt][0] = __float_as_uint(Ws[(ks + ctg) * WSTR + col]);
                b[nt][1] = __float_as_uint(Ws[(ks + ctg + 4) * WSTR + col]);
            }
#pragma unroll
            for (int mt = 0; mt < 2; mt++)
#pragma unroll
                for (int nt = 0; nt < NTILES; nt++)
                    mma_tf32(c[mt][nt], a[mt], b[nt]);
        }
        __syncthreads();
    }

#pragma unroll
    for (int mt = 0; mt < 2; mt++) {
        int r0 = row0 + wm * 32 + mt * 16 + g;
#pragma unroll
        for (int nt = 0; nt < NTILES; nt++) {
            int col = wn * (CPAD / 4) + nt * 8 + 2 * ctg;
            float b0 = bias[col], b1 = bias[col + 1];
            if (r0 < NN)
                *(__nv_bfloat162*)&out[(long)r0 * CPAD + col] =
                    __float22bfloat162_rn(make_float2(
                        fmaxf(c[mt][nt][0] + b0, 0.f), fmaxf(c[mt][nt][1] + b1, 0.f)));
            if (r0 + 8 < NN)
                *(__nv_bfloat162*)&out[(long)(r0 + 8) * CPAD + col] =
                    __float22bfloat162_rn(make_float2(
                        fmaxf(c[mt][nt][2] + b0, 0.f), fmaxf(c[mt][nt][3] + b1, 0.f)));
        }
    }
}

// ---------------- pooling (bf16 in, fp32 accumulate) ----------------
__global__ void k_pool() {    // grid NG, block 224
    int g = blockIdx.x, f = threadIdx.x;
    if (f >= 216) return;
    int v0 = g_goff[g], v1 = g_goff[g + 1];
    float s = 0.f;
    for (int v = v0; v < v1; v++) s += __bfloat162float(g_h3b[(long)v * 224 + f]);
    float cnt = (float)(v1 - v0);
    g_pool[g * 216 + f] = s / fmaxf(cnt, 1.f);
}

// ---------------- tiled MLP head (fp32) ----------------
// mlp1: [256, 216] @ [216, 1024] + bias, relu. grid 128 = 4 row-tiles x 32 col-tiles.
__global__ __launch_bounds__(256) void k_mlp1(const float* __restrict__ Wf1,
                                              const float* __restrict__ bf1) {
    extern __shared__ float smm[];
    float* Pt = smm;            // [64][216]
    float* Wt = smm + 64 * 216; // [216][32]
    int b = blockIdx.x, t = threadIdx.x;
    int bi = b >> 5, bj = b & 31;
    int g0 = bi * 64, c0 = bj * 32;
    for (int i = t; i < 64 * 216; i += 256) {
        int r = i / 216, k = i - r * 216;
        Pt[i] = g_pool[(g0 + r) * 216 + k];
    }
    for (int i = t; i < 216 * 32; i += 256) {
        int k = i >> 5, c = i & 31;
        Wt[i] = Wf1[k * 1024 + c0 + c];
    }
    __syncthreads();
    int c = t & 31, rb = t >> 5;
    float acc[8];
#pragma unroll
    for (int j = 0; j < 8; j++) acc[j] = 0.f;
    for (int k = 0; k < 216; k++) {
        float wv = Wt[k * 32 + c];
#pragma unroll
        for (int j = 0; j < 8; j++)
            acc[j] += Pt[(rb + 8 * j) * 216 + k] * wv;
    }
    float bias = bf1[c0 + c];
#pragma unroll
    for (int j = 0; j < 8; j++)
        g_g1[(g0 + rb + 8 * j) * 1024 + c0 + c] = fmaxf(acc[j] + bias, 0.f);
}

// mlp2: [256, 1024] @ [1024, 128] + bias. grid 16 = 4 row-tiles x 4 col-tiles.
__global__ __launch_bounds__(256) void k_mlp2(const float* __restrict__ Wf2,
                                              const float* __restrict__ bf2,
                                              float* __restrict__ out) {
    __shared__ float At[64 * 128];   // 32KB
    __shared__ float Wt[128 * 32];   // 16KB
    int b = blockIdx.x, t = threadIdx.x;
    int bi = b >> 2, bj = b & 3;
    int g0 = bi * 64, c0 = bj * 32;
    int c = t & 31, rb = t >> 5;
    float acc[8];
#pragma unroll
    for (int j = 0; j < 8; j++) acc[j] = 0.f;
    for (int k0 = 0; k0 < 1024; k0 += 128) {
        for (int i = t; i < 64 * 128; i += 256) {
            int r = i >> 7, k = i & 127;
            At[i] = g_g1[(g0 + r) * 1024 + k0 + k];
        }
        for (int i = t; i < 128 * 32; i += 256) {
            int k = i >> 5, cc = i & 31;
            Wt[i] = Wf2[(k0 + k) * 128 + c0 + cc];
        }
        __syncthreads();
        for (int k = 0; k < 128; k++) {
            float wv = Wt[k * 32 + c];
#pragma unroll
            for (int j = 0; j < 8; j++)
                acc[j] += At[(rb + 8 * j) * 128 + k] * wv;
        }
        __syncthreads();
    }
    float bias = bf2[c0 + c];
#pragma unroll
    for (int j = 0; j < 8; j++)
        out[(g0 + rb + 8 * j) * 128 + c0 + c] = acc[j] + bias;
}

// ---------------- launch ----------------
static int smem_bytes(int KPAD, int CPAD) {
    return (64 * (KPAD + 2) + 56 * (CPAD + 8)) * 4;
}

extern "C" void kernel_launch(void* const* d_in, const int* in_sizes, int n_in,
                              void* d_out, int out_size) {
    const float* x     = (const float*)d_in[0];
    const int*   ei    = (const int*)d_in[1];
    const int*   batch = (const int*)d_in[2];
    const float* W1 = (const float*)d_in[3];
    const float* b1 = (const float*)d_in[4];
    const float* W2 = (const float*)d_in[5];
    const float* b2 = (const float*)d_in[6];
    const float* W3 = (const float*)d_in[7];
    const float* b3 = (const float*)d_in[8];
    const float* Wf1 = (const float*)d_in[9];
    const float* bf1 = (const float*)d_in[10];
    const float* Wf2 = (const float*)d_in[11];
    const float* bf2 = (const float*)d_in[12];
    float* out = (float*)d_out;

    float *agg, *Wp1, *bp1, *Wp2, *bp2, *Wp3, *bp3;
    __nv_bfloat16 *xpb, *h1b, *h2b, *h3b;
    cudaGetSymbolAddress((void**)&xpb, g_xpb);
    cudaGetSymbolAddress((void**)&h1b, g_h1b);
    cudaGetSymbolAddress((void**)&h2b, g_h2b);
    cudaGetSymbolAddress((void**)&h3b, g_h3b);
    cudaGetSymbolAddress((void**)&agg, g_agg);
    cudaGetSymbolAddress((void**)&Wp1, g_Wp1);
    cudaGetSymbolAddress((void**)&bp1, g_bp1);
    cudaGetSymbolAddress((void**)&Wp2, g_Wp2);
    cudaGetSymbolAddress((void**)&bp2, g_bp2);
    cudaGetSymbolAddress((void**)&Wp3, g_Wp3);
    cudaGetSymbolAddress((void**)&bp3, g_bp3);

    cudaFuncSetAttribute(k_gemm_mma<56, 64>,
                         cudaFuncAttributeMaxDynamicSharedMemorySize, smem_bytes(56, 64));
    cudaFuncSetAttribute(k_gemm_mma<56, 128>,
                         cudaFuncAttributeMaxDynamicSharedMemorySize, smem_bytes(56, 128));
    cudaFuncSetAttribute(k_gemm_mma<112, 224>,
                         cudaFuncAttributeMaxDynamicSharedMemorySize, smem_bytes(112, 224));
    int mlp1_smem = (64 * 216 + 216 * 32) * 4;
    cudaFuncSetAttribute(k_mlp1, cudaFuncAttributeMaxDynamicSharedMemorySize, mlp1_smem);

    k_setup<<<(S4 + 255) / 256, 256>>>(x, W1, b1, W2, b2, W3, b3);
    k_pre<<<(NE + NN + 255) / 256, 256>>>(ei, batch);
    k_s1<<<NBLK, 256>>>();
    k_s2<<<1, 512>>>();
    k_s3<<<NBLK, 256>>>();
    k_fill<<<(NT_EDGE + 255) / 256, 256>>>(ei);

    int ablk = (NN * 32 + 255) / 256;
    int gblk = (NN + 63) / 64;
    // layer 1: aggregate xpb (bf16, 64), GEMM 56 -> 64 + relu -> h1b (bf16, 64)
    k_agg64b<<<ablk, 256>>>(xpb, agg);
    k_gemm_mma<56, 64><<<gblk, 256, smem_bytes(56, 64)>>>(agg, Wp1, bp1, h1b);
    // layer 2: aggregate h1b, GEMM 56 -> 128 + relu -> h2b (bf16, 128)
    k_agg64b<<<ablk, 256>>>(h1b, agg);
    k_gemm_mma<56, 128><<<gblk, 256, smem_bytes(56, 128)>>>(agg, Wp2, bp2, h2b);
    // layer 3: aggregate h2b (128), GEMM 112 -> 224 + relu -> h3b (bf16, 224)
    k_agg128b<<<ablk, 256>>>(h2b, agg);
    k_gemm_mma<112, 224><<<gblk, 256, smem_bytes(112, 224)>>>(agg, Wp3, bp3, h3b);

    k_pool<<<NG, 224>>>();
    k_mlp1<<<128, 256, mlp1_smem>>>(Wf1, bf1);
    k_mlp2<<<16, 256>>>(Wf2, bf2, out);
}

// round 11
// speedup vs baseline: 1.1582x; 1.0819x over previous
#include <cuda_runtime.h>
#include <cuda_bf16.h>

#define NN 100000
#define NE 1600000
#define NT_EDGE 1700000   // edges + self loops
#define NG 256
#define NBLK 391          // ceil(NN/256)

// ---------------- scratch (static device allocations; no runtime alloc) ----
__device__ int   g_cnt[NN];               // in-degree WITHOUT self loop
__device__ int   g_fill[NN];
__device__ int   g_rowptr[NN + 1];
__device__ int   g_bsum[NBLK];
__device__ __align__(16) int2  g_edata[NT_EDGE];        // {src, f2i(norm)} by dst
__device__ __align__(256) __nv_bfloat16 g_xpb[NN * 64];  // x padded, bf16, stride 64 (1 line)
__device__ __align__(256) __nv_bfloat16 g_h1b[NN * 64];  // layer1 out bf16 (54 real)
__device__ __align__(256) __nv_bfloat16 g_h2b[NN * 128]; // layer2 out bf16 (108 real)
__device__ __align__(256) __nv_bfloat16 g_h3b[NN * 224]; // layer3 out bf16 (216 real)
__device__ __align__(256) __nv_bfloat16 g_aggb[NN * 112];// aggregation out bf16
__device__ __align__(16) float g_Wp1[56 * 64];
__device__ __align__(16) float g_Wp2[56 * 128];
__device__ __align__(16) float g_Wp3[112 * 224];
__device__ float g_bp1[64], g_bp2[128], g_bp3[224];
__device__ float g_pool[NG * 216];
__device__ int   g_goff[NG + 1];
__device__ float g_g1[NG * 1024];

// ---------------- zero pass (must precede merged atomics) ----------------
__global__ void k_zero() {
    int i = blockIdx.x * blockDim.x + threadIdx.x;
    if (i < NN) { g_cnt[i] = 0; g_fill[i] = 0; }
}

// ---------------- merged preprocessing: counts + boundaries + padW + xpad -
#define PW1 (56 * 64 + 64)
#define PW2 (56 * 128 + 128)
#define PW3 (112 * 224 + 224)
#define M0 NE
#define M1 (M0 + NN)
#define M2 (M1 + PW1)
#define M3 (M2 + PW2)
#define M4 (M3 + PW3)
#define M5 (M4 + NN * 8)

__device__ __forceinline__ void padw_one(int j, const float* W, const float* b,
                                         float* Wp, float* bp, int K, int C,
                                         int KPAD, int CPAD) {
    int tot = KPAD * CPAD;
    if (j < tot) {
        int cc = j % CPAD, kk = j / CPAD;
        Wp[j] = (cc < C && kk < K) ? W[kk * C + cc] : 0.f;
    } else {
        int cc = j - tot;
        bp[cc] = (cc < C) ? b[cc] : 0.f;
    }
}

__global__ void k_merged(const int* __restrict__ ei, const int* __restrict__ batch,
                         const float* __restrict__ x,
                         const float* __restrict__ W1, const float* __restrict__ b1,
                         const float* __restrict__ W2, const float* __restrict__ b2,
                         const float* __restrict__ W3, const float* __restrict__ b3) {
    int i = blockIdx.x * blockDim.x + threadIdx.x;
    if (i < M0) {
        atomicAdd(&g_cnt[ei[NE + i]], 1);
    } else if (i < M1) {
        int j = i - M0;
        int bi = batch[j];
        int bprev = (j > 0) ? batch[j - 1] : -1;
        for (int g = bprev + 1; g <= bi; g++) g_goff[g] = j;
        if (j == NN - 1)
            for (int g = bi + 1; g <= NG; g++) g_goff[g] = NN;
    } else if (i < M2) {
        padw_one(i - M1, W1, b1, g_Wp1, g_bp1, 54, 54, 56, 64);
    } else if (i < M3) {
        padw_one(i - M2, W2, b2, g_Wp2, g_bp2, 54, 108, 56, 128);
    } else if (i < M4) {
        padw_one(i - M3, W3, b3, g_Wp3, g_bp3, 108, 216, 112, 224);
    } else if (i < M5) {
        int j = i - M4;
        int r = j >> 3, cw = (j & 7) * 8;
        __nv_bfloat16 tmp[8];
#pragma unroll
        for (int t = 0; t < 8; t++) {
            int c = cw + t;
            tmp[t] = __float2bfloat16((c < 54) ? x[r * 54 + c] : 0.f);
        }
        *(uint4*)&g_xpb[r * 64 + cw] = *(uint4*)tmp;
    }
}

// ---------------- parallel scan of (cnt+1): block sums -> scan -> local ---
__global__ void k_s1() {            // grid NBLK, block 256
    int b = blockIdx.x, t = threadIdx.x;
    int i = b * 256 + t;
    int v = (i < NN) ? g_cnt[i] + 1 : 0;    // +1 self loop
#pragma unroll
    for (int off = 16; off > 0; off >>= 1)
        v += __shfl_down_sync(0xffffffffu, v, off);
    __shared__ int sm[8];
    if ((t & 31) == 0) sm[t >> 5] = v;
    __syncthreads();
    if (t == 0) {
        int s = 0;
#pragma unroll
        for (int j = 0; j < 8; j++) s += sm[j];
        g_bsum[b] = s;
    }
}

__global__ void k_s2() {            // 1 block, 512 threads: exclusive scan of g_bsum
    __shared__ int p[512];
    int t = threadIdx.x;
    int v = (t < NBLK) ? g_bsum[t] : 0;
    p[t] = v;
    __syncthreads();
    for (int off = 1; off < 512; off <<= 1) {
        int u = (t >= off) ? p[t - off] : 0;
        __syncthreads();
        p[t] += u;
        __syncthreads();
    }
    if (t < NBLK) g_bsum[t] = p[t] - v;   // exclusive
}

__global__ void k_s3() {            // grid NBLK, block 256: local scan + offset
    __shared__ int p[256];
    int b = blockIdx.x, t = threadIdx.x;
    int i = b * 256 + t;
    int v = (i < NN) ? g_cnt[i] + 1 : 0;    // +1 self loop
    p[t] = v;
    __syncthreads();
    for (int off = 1; off < 256; off <<= 1) {
        int u = (t >= off) ? p[t - off] : 0;
        __syncthreads();
        p[t] += u;
        __syncthreads();
    }
    int excl = p[t] - v + g_bsum[b];
    if (i < NN) g_rowptr[i] = excl;
    if (i == NN - 1) g_rowptr[NN] = excl + v;
}

__global__ void k_fill(const int* __restrict__ ei) {
    int i = blockIdx.x * blockDim.x + threadIdx.x;
    if (i >= NT_EDGE) return;
    int r, c;
    if (i < NE) { r = ei[i]; c = ei[NE + i]; }
    else        { r = c = i - NE; }
    float nrm = rsqrtf((float)(g_cnt[r] + 1) * (float)(g_cnt[c] + 1));
    int pos = g_rowptr[c] + atomicAdd(&g_fill[c], 1);
    g_edata[pos] = make_int2(r, __float_as_int(nrm));
}

// ---------------- aggregation (bf16 gather, fp32 acc, bf16 out) -----------
__device__ __forceinline__ void acc8(float acc[8], float nrm, uint4 t) {
    float2 f0 = __bfloat1622float2(*(__nv_bfloat162*)&t.x);
    float2 f1 = __bfloat1622float2(*(__nv_bfloat162*)&t.y);
    float2 f2 = __bfloat1622float2(*(__nv_bfloat162*)&t.z);
    float2 f3 = __bfloat1622float2(*(__nv_bfloat162*)&t.w);
    acc[0] += nrm * f0.x; acc[1] += nrm * f0.y;
    acc[2] += nrm * f1.x; acc[3] += nrm * f1.y;
    acc[4] += nrm * f2.x; acc[5] += nrm * f2.y;
    acc[6] += nrm * f3.x; acc[7] += nrm * f3.y;
}

__device__ __forceinline__ uint4 pack8(const float acc[8]) {
    uint4 r;
    *(__nv_bfloat162*)&r.x = __float22bfloat162_rn(make_float2(acc[0], acc[1]));
    *(__nv_bfloat162*)&r.y = __float22bfloat162_rn(make_float2(acc[2], acc[3]));
    *(__nv_bfloat162*)&r.z = __float22bfloat162_rn(make_float2(acc[4], acc[5]));
    *(__nv_bfloat162*)&r.w = __float22bfloat162_rn(make_float2(acc[6], acc[7]));
    return r;
}

// 64-bf16 rows (128B = 1 line). 8 edges/warp-iter. bf16 out rows stride 64.
__global__ void k_agg64b(const __nv_bfloat16* __restrict__ in,
                         __nv_bfloat16* __restrict__ out) {
    int w = (blockIdx.x * blockDim.x + threadIdx.x) >> 5;
    int lane = threadIdx.x & 31;
    if (w >= NN) return;
    int q = lane >> 3, sl = lane & 7;
    int e0 = g_rowptr[w], e1 = g_rowptr[w + 1];
    float acc[8];
#pragma unroll
    for (int j = 0; j < 8; j++) acc[j] = 0.f;
    for (int e = e0; e < e1; e += 8) {
        int i0 = e + q, i1 = e + 4 + q;
        bool v0 = i0 < e1, v1 = i1 < e1;
        int2 ed0 = __ldg(&g_edata[v0 ? i0 : e]);
        int2 ed1 = __ldg(&g_edata[v1 ? i1 : e]);
        float n0 = v0 ? __int_as_float(ed0.y) : 0.f;
        float n1 = v1 ? __int_as_float(ed1.y) : 0.f;
        const uint4* s0 = (const uint4*)(in + (long)ed0.x * 64);
        const uint4* s1 = (const uint4*)(in + (long)ed1.x * 64);
        uint4 t0 = __ldg(&s0[sl]);
        uint4 t1 = __ldg(&s1[sl]);
        acc8(acc, n0, t0);
        acc8(acc, n1, t1);
    }
#pragma unroll
    for (int j = 0; j < 8; j++) {
        acc[j] += __shfl_xor_sync(0xffffffffu, acc[j], 8);
        acc[j] += __shfl_xor_sync(0xffffffffu, acc[j], 16);
    }
    if (q == 0)   // all 8 sl active: full 64-el row (cols 54-63 are zeros)
        ((uint4*)(out + (long)w * 64))[sl] = pack8(acc);
}

// 128-bf16 rows (256B = 2 lines). 4 edges/warp-iter. bf16 out rows stride 112.
__global__ void k_agg128b(const __nv_bfloat16* __restrict__ in,
                          __nv_bfloat16* __restrict__ out) {
    int w = (blockIdx.x * blockDim.x + threadIdx.x) >> 5;
    int lane = threadIdx.x & 31;
    if (w >= NN) return;
    int half = lane >> 4, sl = lane & 15;
    int e0 = g_rowptr[w], e1 = g_rowptr[w + 1];
    float acc[8];
#pragma unroll
    for (int j = 0; j < 8; j++) acc[j] = 0.f;
    for (int e = e0; e < e1; e += 4) {
        int i0 = e + half, i1 = e + 2 + half;
        bool v0 = i0 < e1, v1 = i1 < e1;
        int2 ed0 = __ldg(&g_edata[v0 ? i0 : e]);
        int2 ed1 = __ldg(&g_edata[v1 ? i1 : e]);
        float n0 = v0 ? __int_as_float(ed0.y) : 0.f;
        float n1 = v1 ? __int_as_float(ed1.y) : 0.f;
        const uint4* s0 = (const uint4*)(in + (long)ed0.x * 128);
        const uint4* s1 = (const uint4*)(in + (long)ed1.x * 128);
        uint4 t0 = __ldg(&s0[sl]);
        uint4 t1 = __ldg(&s1[sl]);
        acc8(acc, n0, t0);
        acc8(acc, n1, t1);
    }
#pragma unroll
    for (int j = 0; j < 8; j++)
        acc[j] += __shfl_xor_sync(0xffffffffu, acc[j], 16);
    if (half == 0 && sl < 14)   // 112-el row
        ((uint4*)(out + (long)w * 112))[sl] = pack8(acc);
}

// ---------------- tf32 tensor-core GEMM (A staged from bf16), bf16 out ----
__device__ __forceinline__ unsigned f2tf(float v) {
    unsigned u;
    asm("cvt.rna.tf32.f32 %0, %1;" : "=r"(u) : "f"(v));
    return u;
}

__device__ __forceinline__ void mma_tf32(float c[4], const unsigned a[4], const unsigned b[2]) {
    asm volatile(
        "mma.sync.aligned.m16n8k8.row.col.f32.tf32.tf32.f32 "
        "{%0,%1,%2,%3}, {%4,%5,%6,%7}, {%8,%9}, {%0,%1,%2,%3};\n"
        : "+f"(c[0]), "+f"(c[1]), "+f"(c[2]), "+f"(c[3])
        : "r"(a[0]), "r"(a[1]), "r"(a[2]), "r"(a[3]), "r"(b[0]), "r"(b[1]));
}

// A: bf16 rows of stride SRCSTR (>= KPAD), first KPAD cols used.
template <int KPAD, int CPAD, int SRCSTR>
__global__ __launch_bounds__(256)
void k_gemm_mma(const __nv_bfloat16* __restrict__ A, const float* __restrict__ W,
                const float* __restrict__ bias, __nv_bfloat16* __restrict__ out) {
    extern __shared__ float sm[];
    constexpr int ASTR = KPAD + 2;
    constexpr int WSTR = CPAD + 8;
    constexpr int KCH = 56;
    constexpr int NTILES = CPAD / 32;
    float* As = sm;                       // [64][ASTR]
    float* Ws = sm + 64 * ASTR;           // [KCH][WSTR]

    int tid = threadIdx.x;
    int w = tid >> 5, lane = tid & 31;
    int g = lane >> 2, ctg = lane & 3;
    int wm = w & 1, wn = w >> 1;
    int row0 = blockIdx.x * 64;

    float c[2][NTILES][4];
#pragma unroll
    for (int mt = 0; mt < 2; mt++)
#pragma unroll
        for (int nt = 0; nt < NTILES; nt++)
#pragma unroll
            for (int i = 0; i < 4; i++) c[mt][nt][i] = 0.f;

    // stage A: bf16 -> tf32 (KPAD % 8 == 0, 8 els per thread-chunk)
    for (int i = tid * 8; i < 64 * KPAD; i += 256 * 8) {
        int r = i / KPAD, k = i % KPAD;
        uint4 v = make_uint4(0u, 0u, 0u, 0u);
        if (row0 + r < NN) v = *(const uint4*)&A[(long)(row0 + r) * SRCSTR + k];
        const __nv_bfloat16* hb = (const __nv_bfloat16*)&v;
        float* o = As + r * ASTR + k;
#pragma unroll
        for (int t = 0; t < 8; t++)
            o[t] = __uint_as_float(f2tf(__bfloat162float(hb[t])));
    }

#pragma unroll 1
    for (int kc = 0; kc < KPAD; kc += KCH) {
        constexpr int kchunk = (KPAD < KCH) ? KPAD : KCH;
        for (int i = tid * 4; i < kchunk * CPAD; i += 256 * 4) {
            int kk = i / CPAD, cc = i % CPAD;
            float4 v = *(const float4*)&W[(long)(kc + kk) * CPAD + cc];
            float4 t;
            t.x = __uint_as_float(f2tf(v.x));
            t.y = __uint_as_float(f2tf(v.y));
            t.z = __uint_as_float(f2tf(v.z));
            t.w = __uint_as_float(f2tf(v.w));
            *(float4*)&Ws[kk * WSTR + cc] = t;
        }
        __syncthreads();

#pragma unroll
        for (int ks = 0; ks < kchunk; ks += 8) {
            unsigned a[2][4];
#pragma unroll
            for (int mt = 0; mt < 2; mt++) {
                int ar = wm * 32 + mt * 16;
                int kb = kc + ks + ctg;
                a[mt][0] = __float_as_uint(As[(ar + g) * ASTR + kb]);
                a[mt][1] = __float_as_uint(As[(ar + g + 8) * ASTR + kb]);
                a[mt][2] = __float_as_uint(As[(ar + g) * ASTR + kb + 4]);
                a[mt][3] = __float_as_uint(As[(ar + g + 8) * ASTR + kb + 4]);
            }
            unsigned b[NTILES][2];
#pragma unroll
            for (int nt = 0; nt < NTILES; nt++) {
                int col = wn * (CPAD / 4) + nt * 8 + g;
                b[nt][0] = __float_as_uint(Ws[(ks + ctg) * WSTR + col]);
                b[nt][1] = __float_as_uint(Ws[(ks + ctg + 4) * WSTR + col]);
            }
#pragma unroll
            for (int mt = 0; mt < 2; mt++)
#pragma unroll
                for (int nt = 0; nt < NTILES; nt++)
                    mma_tf32(c[mt][nt], a[mt], b[nt]);
        }
        __syncthreads();
    }

#pragma unroll
    for (int mt = 0; mt < 2; mt++) {
        int r0 = row0 + wm * 32 + mt * 16 + g;
#pragma unroll
        for (int nt = 0; nt < NTILES; nt++) {
            int col = wn * (CPAD / 4) + nt * 8 + 2 * ctg;
            float b0 = bias[col], b1 = bias[col + 1];
            if (r0 < NN)
                *(__nv_bfloat162*)&out[(long)r0 * CPAD + col] =
                    __float22bfloat162_rn(make_float2(
                        fmaxf(c[mt][nt][0] + b0, 0.f), fmaxf(c[mt][nt][1] + b1, 0.f)));
            if (r0 + 8 < NN)
                *(__nv_bfloat162*)&out[(long)(r0 + 8) * CPAD + col] =
                    __float22bfloat162_rn(make_float2(
                        fmaxf(c[mt][nt][2] + b0, 0.f), fmaxf(c[mt][nt][3] + b1, 0.f)));
        }
    }
}

// ---------------- pooling (bf16 in, fp32 accumulate) ----------------
__global__ void k_pool() {    // grid NG, block 224
    int g = blockIdx.x, f = threadIdx.x;
    if (f >= 216) return;
    int v0 = g_goff[g], v1 = g_goff[g + 1];
    float s = 0.f;
    for (int v = v0; v < v1; v++) s += __bfloat162float(g_h3b[(long)v * 224 + f]);
    float cnt = (float)(v1 - v0);
    g_pool[g * 216 + f] = s / fmaxf(cnt, 1.f);
}

// ---------------- tiled MLP head (fp32) ----------------
__global__ __launch_bounds__(256) void k_mlp1(const float* __restrict__ Wf1,
                                              const float* __restrict__ bf1) {
    extern __shared__ float smm[];
    float* Pt = smm;            // [64][216]
    float* Wt = smm + 64 * 216; // [216][32]
    int b = blockIdx.x, t = threadIdx.x;
    int bi = b >> 5, bj = b & 31;
    int g0 = bi * 64, c0 = bj * 32;
    for (int i = t; i < 64 * 216; i += 256) {
        int r = i / 216, k = i - r * 216;
        Pt[i] = g_pool[(g0 + r) * 216 + k];
    }
    for (int i = t; i < 216 * 32; i += 256) {
        int k = i >> 5, c = i & 31;
        Wt[i] = Wf1[k * 1024 + c0 + c];
    }
    __syncthreads();
    int c = t & 31, rb = t >> 5;
    float acc[8];
#pragma unroll
    for (int j = 0; j < 8; j++) acc[j] = 0.f;
    for (int k = 0; k < 216; k++) {
        float wv = Wt[k * 32 + c];
#pragma unroll
        for (int j = 0; j < 8; j++)
            acc[j] += Pt[(rb + 8 * j) * 216 + k] * wv;
    }
    float bias = bf1[c0 + c];
#pragma unroll
    for (int j = 0; j < 8; j++)
        g_g1[(g0 + rb + 8 * j) * 1024 + c0 + c] = fmaxf(acc[j] + bias, 0.f);
}

__global__ __launch_bounds__(256) void k_mlp2(const float* __restrict__ Wf2,
                                              const float* __restrict__ bf2,
                                              float* __restrict__ out) {
    __shared__ float At[64 * 128];   // 32KB
    __shared__ float Wt[128 * 32];   // 16KB
    int b = blockIdx.x, t = threadIdx.x;
    int bi = b >> 2, bj = b & 3;
    int g0 = bi * 64, c0 = bj * 32;
    int c = t & 31, rb = t >> 5;
    float acc[8];
#pragma unroll
    for (int j = 0; j < 8; j++) acc[j] = 0.f;
    for (int k0 = 0; k0 < 1024; k0 += 128) {
        for (int i = t; i < 64 * 128; i += 256) {
            int r = i >> 7, k = i & 127;
            At[i] = g_g1[(g0 + r) * 1024 + k0 + k];
        }
        for (int i = t; i < 128 * 32; i += 256) {
            int k = i >> 5, cc = i & 31;
            Wt[i] = Wf2[(k0 + k) * 128 + c0 + cc];
        }
        __syncthreads();
        for (int k = 0; k < 128; k++) {
            float wv = Wt[k * 32 + c];
#pragma unroll
            for (int j = 0; j < 8; j++)
                acc[j] += At[(rb + 8 * j) * 128 + k] * wv;
        }
        __syncthreads();
    }
    float bias = bf2[c0 + c];
#pragma unroll
    for (int j = 0; j < 8; j++)
        out[(g0 + rb + 8 * j) * 128 + c0 + c] = acc[j] + bias;
}

// ---------------- launch ----------------
static int smem_bytes(int KPAD, int CPAD) {
    return (64 * (KPAD + 2) + 56 * (CPAD + 8)) * 4;
}

extern "C" void kernel_launch(void* const* d_in, const int* in_sizes, int n_in,
                              void* d_out, int out_size) {
    const float* x     = (const float*)d_in[0];
    const int*   ei    = (const int*)d_in[1];
    const int*   batch = (const int*)d_in[2];
    const float* W1 = (const float*)d_in[3];
    const float* b1 = (const float*)d_in[4];
    const float* W2 = (const float*)d_in[5];
    const float* b2 = (const float*)d_in[6];
    const float* W3 = (const float*)d_in[7];
    const float* b3 = (const float*)d_in[8];
    const float* Wf1 = (const float*)d_in[9];
    const float* bf1 = (const float*)d_in[10];
    const float* Wf2 = (const float*)d_in[11];
    const float* bf2 = (const float*)d_in[12];
    float* out = (float*)d_out;

    float *Wp1, *bp1, *Wp2, *bp2, *Wp3, *bp3;
    __nv_bfloat16 *xpb, *h1b, *h2b, *h3b, *aggb;
    cudaGetSymbolAddress((void**)&xpb, g_xpb);
    cudaGetSymbolAddress((void**)&h1b, g_h1b);
    cudaGetSymbolAddress((void**)&h2b, g_h2b);
    cudaGetSymbolAddress((void**)&h3b, g_h3b);
    cudaGetSymbolAddress((void**)&aggb, g_aggb);
    cudaGetSymbolAddress((void**)&Wp1, g_Wp1);
    cudaGetSymbolAddress((void**)&bp1, g_bp1);
    cudaGetSymbolAddress((void**)&Wp2, g_Wp2);
    cudaGetSymbolAddress((void**)&bp2, g_bp2);
    cudaGetSymbolAddress((void**)&Wp3, g_Wp3);
    cudaGetSymbolAddress((void**)&bp3, g_bp3);

    cudaFuncSetAttribute(k_gemm_mma<56, 64, 64>,
                         cudaFuncAttributeMaxDynamicSharedMemorySize, smem_bytes(56, 64));
    cudaFuncSetAttribute(k_gemm_mma<56, 128, 64>,
                         cudaFuncAttributeMaxDynamicSharedMemorySize, smem_bytes(56, 128));
    cudaFuncSetAttribute(k_gemm_mma<112, 224, 112>,
                         cudaFuncAttributeMaxDynamicSharedMemorySize, smem_bytes(112, 224));
    int mlp1_smem = (64 * 216 + 216 * 32) * 4;
    cudaFuncSetAttribute(k_mlp1, cudaFuncAttributeMaxDynamicSharedMemorySize, mlp1_smem);

    k_zero<<<NBLK, 256>>>();
    k_merged<<<(M5 + 255) / 256, 256>>>(ei, batch, x, W1, b1, W2, b2, W3, b3);
    k_s1<<<NBLK, 256>>>();
    k_s2<<<1, 512>>>();
    k_s3<<<NBLK, 256>>>();
    k_fill<<<(NT_EDGE + 255) / 256, 256>>>(ei);

    int ablk = (NN * 32 + 255) / 256;
    int gblk = (NN + 63) / 64;
    // layer 1: aggregate xpb -> aggb (bf16,64), GEMM 56 -> 64 + relu -> h1b
    k_agg64b<<<ablk, 256>>>(xpb, aggb);
    k_gemm_mma<56, 64, 64><<<gblk, 256, smem_bytes(56, 64)>>>(aggb, Wp1, bp1, h1b);
    // layer 2: aggregate h1b -> aggb (bf16,64), GEMM 56 -> 128 + relu -> h2b
    k_agg64b<<<ablk, 256>>>(h1b, aggb);
    k_gemm_mma<56, 128, 64><<<gblk, 256, smem_bytes(56, 128)>>>(aggb, Wp2, bp2, h2b);
    // layer 3: aggregate h2b -> aggb (bf16,112), GEMM 112 -> 224 + relu -> h3b
    k_agg128b<<<ablk, 256>>>(h2b, aggb);
    k_gemm_mma<112, 224, 112><<<gblk, 256, smem_bytes(112, 224)>>>(aggb, Wp3, bp3, h3b);

    k_pool<<<NG, 224>>>();
    k_mlp1<<<128, 256, mlp1_smem>>>(Wf1, bf1);
    k_mlp2<<<16, 256>>>(Wf2, bf2, out);
}